// round 15
// baseline (speedup 1.0000x reference)
#include <cuda_runtime.h>
#include <cuda_fp16.h>
#include <cstddef>
#include <cstdint>

// Problem constants
#define Bq   2
#define Sq   2048
#define Eq   1024
#define Hq   16
#define Dq   64
#define Mq   (Bq*Sq)          // 4096

// ---------------------------------------------------------------------------
// Scratch (device globals; no allocations allowed)
// ---------------------------------------------------------------------------
__device__ unsigned g_xA  [(size_t)Mq*Eq/2];     // x   as GEMM-A frags
__device__ unsigned g_attA[(size_t)Mq*Eq/2];     // att as GEMM-A frags
__device__ unsigned g_qF  [(size_t)Mq*Eq/2];     // q   as attn-Q frags (scaled)
__device__ unsigned g_xK  [(size_t)Mq*Eq/2];     // x   as attn-K frags
__device__ unsigned g_vV  [(size_t)Mq*Eq/2];     // v   as attn-V frags
__device__ unsigned g_wqA [(size_t)Eq*Eq/2];     // Wq   as GEMM-A frags
__device__ unsigned g_wqvB[(size_t)Eq*2*Eq/2];   // W' | Wv as B-frags (2048 n)
__device__ unsigned g_wkB [(size_t)Eq*Eq/2];     // Wk   as B-frags
__device__ unsigned g_wpB [(size_t)Eq*Eq/2];     // Wp   as B-frags
__device__ float    g_wpart[(size_t)8*Eq*Eq];    // W' split-K fp32 partials
__device__ float    g_bqv [2 * Eq];              // b' | vb fused bias

// ---------------------------------------------------------------------------
// helpers
// ---------------------------------------------------------------------------
__device__ __forceinline__ unsigned packh2(float lo, float hi) {
    unsigned r;
    asm("cvt.rn.f16x2.f32 %0, %1, %2;" : "=r"(r) : "f"(hi), "f"(lo));
    return r;
}
__device__ __forceinline__ unsigned ex2h2(unsigned a) {
    unsigned r;
    asm("ex2.approx.f16x2 %0, %1;" : "=r"(r) : "r"(a));
    return r;
}
__device__ __forceinline__ void mma_f16(float* c, const unsigned* a, const unsigned* b) {
    asm volatile(
        "mma.sync.aligned.m16n8k16.row.col.f32.f16.f16.f32 "
        "{%0,%1,%2,%3}, {%4,%5,%6,%7}, {%8,%9}, {%0,%1,%2,%3};"
        : "+f"(c[0]), "+f"(c[1]), "+f"(c[2]), "+f"(c[3])
        : "r"(a[0]), "r"(a[1]), "r"(a[2]), "r"(a[3]),
          "r"(b[0]), "r"(b[1]));
}
__device__ __forceinline__ void cpasync16(uint32_t s, const void* g) {
    asm volatile("cp.async.cg.shared.global [%0], [%1], 16;" :: "r"(s), "l"(g));
}
__device__ __forceinline__ void cp_commit() {
    asm volatile("cp.async.commit_group;");
}

// ---------------------------------------------------------------------------
// fp16 fragment-store helpers (validated)
// ---------------------------------------------------------------------------
__device__ __forceinline__ void store_Afrag16(unsigned* C, int row, int k,
                                              float v0, float v1) {
    size_t tile = (size_t)(row >> 7) * 32 + (k >> 5);
    int m = row & 127, klo = k & 15, kstep = (k >> 4) & 1;
    int inner = ((kstep * 8 + (m >> 4)) * 32 + (m & 7) * 4 + ((klo >> 1) & 3)) * 4
              + ((m >> 3) & 1) + 2 * (klo >> 3);
    C[tile * 2048 + inner] = packh2(v0, v1);
}
// attn Q-frag: pre-scaled by (1/8)*log2(e) so attention uses ex2 directly
__device__ __forceinline__ void store_Qfrag16(unsigned* C, int row, int col,
                                              float v0, float v1) {
    const float QS = 0.125f * 1.4426950408889634f;
    int b = row >> 11, s2 = row & 2047, qt = s2 >> 7, sr = s2 & 127;
    int h = col >> 6, d = col & 63;
    size_t tile = (size_t)((b << 4) + h) * 16 + qt;
    int dlo = d & 15, kstep = d >> 4;
    int inner = ((kstep * 8 + (sr >> 4)) * 32 + (sr & 7) * 4 + ((dlo >> 1) & 3)) * 4
              + ((sr >> 3) & 1) + 2 * (dlo >> 3);
    C[tile * 4096 + inner] = packh2(v0 * QS, v1 * QS);
}
__device__ __forceinline__ void store_Vfrag16(__half* C16, int row, int col, float val) {
    int b = row >> 11, s2 = row & 2047, kt = s2 >> 6, kp = s2 & 63;
    int h = col >> 6, d = col & 63;
    size_t tile = (size_t)((b << 4) + h) * 32 + kt;
    int klo = kp & 15, kstep = kp >> 4;
    int inner = ((kstep * 8 + (d >> 3)) * 32 + (d & 7) * 4 + ((klo >> 1) & 3)) * 2
              + (klo >> 3);
    C16[tile * 4096 + inner * 2 + (klo & 1)] = __float2half_rn(val);
}

// ---------------------------------------------------------------------------
// Conversion bodies (validated)
// ---------------------------------------------------------------------------
__device__ __forceinline__ void convB_body(const float* B, unsigned* dst, int ldb, int idx)
{
    int k  = idx >> 8;
    int n4 = (idx & 255) << 2;
    float4 t = *(const float4*)(B + (size_t)k * ldb + n4);
    float tv[4] = {t.x, t.y, t.z, t.w};
    int klo = k & 15, kstep = (k >> 4) & 1;
    __half* d16 = (__half*)dst;
    #pragma unroll
    for (int j = 0; j < 4; j++) {
        int n = n4 + j;
        size_t tile = ((size_t)(n >> 8) * 32 + (k >> 5));
        int inner = ((kstep * 32 + ((n >> 3) & 31)) * 32 + (n & 7) * 4 + ((klo >> 1) & 3)) * 2
                  + (klo >> 3);
        d16[tile * 8192 + inner * 2 + (klo & 1)] = __float2half_rn(tv[j]);
    }
}
__device__ __forceinline__ void convBT_body(const float* B, unsigned* dst, int ldb, int idx)
{
    int n  = idx >> 8;
    int k4 = (idx & 255) << 2;
    float4 t = *(const float4*)(B + (size_t)n * ldb + k4);
    int nfrag = (n >> 3) & 31, g = n & 7;
    #pragma unroll
    for (int p = 0; p < 2; p++) {
        int k = k4 + 2 * p;
        int klo = k & 15, kstep = (k >> 4) & 1;
        size_t tile = ((size_t)(n >> 8) * 32 + (k >> 5));
        int inner = ((kstep * 32 + nfrag) * 32 + g * 4 + ((klo >> 1) & 3)) * 2
                  + (klo >> 3);
        dst[tile * 4096 + inner] = (p == 0) ? packh2(t.x, t.y) : packh2(t.z, t.w);
    }
}

// ---------------------------------------------------------------------------
// convW1: only what the W' chain needs (Wq -> A-frags, Wk -> B-frags)
// ---------------------------------------------------------------------------
__global__ void convW1(const float* __restrict__ aw,
                       unsigned* __restrict__ wqA, unsigned* __restrict__ wk)
{
    int bx = blockIdx.x;
    int which = bx >> 10;
    int idx = (bx & 1023) * 256 + threadIdx.x;
    if (which == 0) {
        int m = idx >> 8, n4 = (idx & 255) << 2;
        float4 t = *(const float4*)(aw + (size_t)m * 3072 + n4);
        store_Afrag16(wqA, m, n4,     t.x, t.y);
        store_Afrag16(wqA, m, n4 + 2, t.z, t.w);
    } else {
        convBT_body(aw + Eq, wk, 3 * Eq, idx);
    }
}

// ---------------------------------------------------------------------------
// convX2: x conversion + Wv/Wp conversion + vb copy.
// blocks 0..4095 x; 4096..5119 Wv; 5120..6143 Wp; 6144..6147 vb
// ---------------------------------------------------------------------------
__global__ void convX2(const float* __restrict__ x,
                       const float* __restrict__ aw, const float* __restrict__ pw,
                       const float* __restrict__ ab,
                       unsigned* __restrict__ xA, unsigned* __restrict__ xK,
                       unsigned* __restrict__ wqv, unsigned* __restrict__ wp,
                       float* __restrict__ bqv)
{
    int bx = blockIdx.x;
    if (bx >= 4096) {
        if (bx < 5120) {
            convB_body(aw + 2 * Eq, wqv + (size_t)4 * 32 * 4096, 3 * Eq,
                       (bx - 4096) * 256 + threadIdx.x);
        } else if (bx < 6144) {
            convB_body(pw, wp, Eq, (bx - 5120) * 256 + threadIdx.x);
        } else {
            int i = (bx - 6144) * 256 + threadIdx.x;
            bqv[1024 + i] = ab[2048 + i];
        }
        return;
    }
    int idx = bx * 256 + threadIdx.x;
    int m   = idx >> 8;
    int e4  = (idx & 255) << 2;
    float4 t = *(const float4*)(x + (size_t)m * Eq + e4);

    store_Afrag16(xA, m, e4,     t.x, t.y);
    store_Afrag16(xA, m, e4 + 2, t.z, t.w);

    int s = m & (Sq - 1), b = m >> 11;
    int h = e4 >> 6, d4 = e4 & 63;
    int kt = s >> 6, kp = s & 63;
    unsigned* tile = xK + ((size_t)((b << 4) + h) * 32 + kt) * 2048;
    float tv[4] = {t.x, t.y, t.z, t.w};
    #pragma unroll
    for (int p = 0; p < 2; p++) {
        int d = d4 + 2 * p;
        int dlo = d & 15, kstep = d >> 4;
        int inner = ((kstep * 8 + (kp >> 3)) * 32 + (kp & 7) * 4 + ((dlo >> 1) & 3)) * 2
                  + (dlo >> 3);
        tile[inner] = packh2(tv[2 * p], tv[2 * p + 1]);
    }
}

// ---------------------------------------------------------------------------
// W' finalize: blocks 0..1023 sum 8 split-K partials -> B-frags (wqv 1st half)
//              blocks 1024..2047 compute b'[j] = bq . Wk[j,:] + kb[j]
// ---------------------------------------------------------------------------
__global__ void convWp(const float* __restrict__ wpart,
                       const float* __restrict__ aw, const float* __restrict__ ab,
                       unsigned* __restrict__ wqv, float* __restrict__ bqv)
{
    int bx = blockIdx.x;
    if (bx < 1024) {
        int idx = bx * 256 + threadIdx.x;
        int k = idx >> 8, n4 = (idx & 255) << 2;
        size_t off = (size_t)k * 1024 + n4;
        float tv[4] = {0.f, 0.f, 0.f, 0.f};
        #pragma unroll
        for (int z = 0; z < 8; z++) {
            float4 p = *(const float4*)(wpart + off + (size_t)z * 1048576);
            tv[0] += p.x; tv[1] += p.y; tv[2] += p.z; tv[3] += p.w;
        }
        int klo = k & 15, kstep = (k >> 4) & 1;
        __half* d16 = (__half*)wqv;
        #pragma unroll
        for (int j = 0; j < 4; j++) {
            int n = n4 + j;
            size_t tile = ((size_t)(n >> 8) * 32 + (k >> 5));
            int inner = ((kstep * 32 + ((n >> 3) & 31)) * 32 + (n & 7) * 4
                         + ((klo >> 1) & 3)) * 2 + (klo >> 3);
            d16[tile * 8192 + inner * 2 + (klo & 1)] = __float2half_rn(tv[j]);
        }
        return;
    }
    // b'[j]
    int j = bx - 1024;
    __shared__ float red[256];
    int tid = threadIdx.x;
    float sum = 0.f;
    #pragma unroll
    for (int i = 0; i < 4; i++) {
        int n = tid + i * 256;
        sum += ab[n] * aw[(size_t)j * 3072 + 1024 + n];
    }
    red[tid] = sum;
    __syncthreads();
    for (int s = 128; s > 0; s >>= 1) {
        if (tid < s) red[tid] += red[tid + s];
        __syncthreads();
    }
    if (tid == 0) bqv[j] = red[0] + ab[1024 + j];
}

// ---------------------------------------------------------------------------
// GEMM fp16: CTA 128m x 128n, K-stage 64, 3-stage cp.async, 256 thr, 2 CTA/SM.
// MODE: 0 = fp32 row-major (+bias)
//       5 = dual: col<1024 -> Q-frag to Cv, else V-frag to Cv2 (+bias)
//       7 = fp32 partial to Cv + z*1M, no bias, kbase = z*nst
// ---------------------------------------------------------------------------
template<int MODE>
__global__ void __launch_bounds__(256, 2) gemm_frag(
    const unsigned* __restrict__ Afrag, const unsigned* __restrict__ Bfrag,
    const float* __restrict__ bias, void* __restrict__ Cv, void* __restrict__ Cv2,
    int nst)
{
    extern __shared__ unsigned sh[];              // 3 * 8192 uints = 96 KB
    const int tid  = threadIdx.x;
    const int lane = tid & 31;
    const int wid  = tid >> 5;
    const int wm   = wid & 1;
    const int wn   = wid >> 1;
    const int g    = lane >> 2;
    const int tig  = lane & 3;
    const int m0   = blockIdx.y * 128;
    const int n0   = blockIdx.x * 128;
    const int nhalf = blockIdx.x & 1;
    const int kbase = (MODE == 7) ? blockIdx.z * nst : 0;

    const unsigned* gA = Afrag + (size_t)blockIdx.y * 32 * 2048;
    const unsigned* gB = Bfrag + (size_t)(blockIdx.x >> 1) * 32 * 4096;
    const uint32_t sbase = (uint32_t)__cvta_generic_to_shared(sh);

    auto issue = [&](int st) {
        int sl = st % 3;
        uint32_t sa = sbase + sl * 8192 * 4;
        const unsigned* ga = gA + (size_t)(2 * (kbase + st)) * 2048;
        #pragma unroll
        for (int i = 0; i < 4; i++)
            cpasync16(sa + (tid + i * 256) * 16, ga + (tid + i * 256) * 4);
        uint32_t sb = sa + 4096 * 4;
        #pragma unroll
        for (int c = 0; c < 4; c++) {
            int h = c >> 1, kst = c & 1;
            const unsigned* gb = gB + (size_t)(2 * (kbase + st) + h) * 4096
                               + kst * 2048 + nhalf * 1024;
            cpasync16(sb + (c * 1024 + tid * 4) * 4, gb + tid * 4);
        }
        cp_commit();
    };

    float acc[4][4][4];
    #pragma unroll
    for (int mi = 0; mi < 4; mi++)
        #pragma unroll
        for (int ni = 0; ni < 4; ni++)
            #pragma unroll
            for (int r = 0; r < 4; r++) acc[mi][ni][r] = 0.f;

    issue(0);
    issue(1);

    for (int st = 0; st < nst; st++) {
        if (st == nst - 1) asm volatile("cp.async.wait_group 0;");
        else               asm volatile("cp.async.wait_group 1;");
        __syncthreads();

        const unsigned* stage = sh + (st % 3) * 8192;
        #pragma unroll
        for (int half = 0; half < 2; half++) {
            const unsigned* as = stage + half * 2048;
            const unsigned* bs = stage + 4096 + half * 2048;
            #pragma unroll
            for (int ks = 0; ks < 2; ks++) {
                unsigned af[4][4], bf[4][2];
                #pragma unroll
                for (int mi = 0; mi < 4; mi++) {
                    uint4 t = *(const uint4*)(as + ((ks * 8 + wm * 4 + mi) * 32 + lane) * 4);
                    af[mi][0] = t.x; af[mi][1] = t.y; af[mi][2] = t.z; af[mi][3] = t.w;
                }
                #pragma unroll
                for (int ni = 0; ni < 4; ni++) {
                    uint2 t = *(const uint2*)(bs + ks * 1024
                                              + ((wn * 4 + ni) * 32 + lane) * 2);
                    bf[ni][0] = t.x; bf[ni][1] = t.y;
                }
                #pragma unroll
                for (int mi = 0; mi < 4; mi++)
                    #pragma unroll
                    for (int ni = 0; ni < 4; ni++)
                        mma_f16(acc[mi][ni], af[mi], bf[ni]);
            }
        }

        if (st + 2 < nst) issue(st + 2);
    }

    // epilogue
    #pragma unroll
    for (int ni = 0; ni < 4; ni++) {
        int col = n0 + wn * 32 + ni * 8 + 2 * tig;
        float b0 = 0.f, b1 = 0.f;
        if (MODE != 7) { b0 = bias[col]; b1 = bias[col + 1]; }
        #pragma unroll
        for (int mi = 0; mi < 4; mi++) {
            int row = m0 + wm * 64 + mi * 16 + g;
            float v0 = acc[mi][ni][0] + b0, v1 = acc[mi][ni][1] + b1;
            float v2 = acc[mi][ni][2] + b0, v3 = acc[mi][ni][3] + b1;
            if (MODE == 0) {
                float* C = (float*)Cv;
                *(float2*)(C + (size_t)row * Eq + col)       = make_float2(v0, v1);
                *(float2*)(C + (size_t)(row + 8) * Eq + col) = make_float2(v2, v3);
            } else if (MODE == 7) {
                float* C = (float*)Cv + (size_t)blockIdx.z * 1048576;
                *(float2*)(C + (size_t)row * Eq + col)       = make_float2(v0, v1);
                *(float2*)(C + (size_t)(row + 8) * Eq + col) = make_float2(v2, v3);
            } else {    // MODE 5: dual Q | V
                if (col < 1024) {
                    unsigned* C = (unsigned*)Cv;
                    store_Qfrag16(C, row,     col, v0, v1);
                    store_Qfrag16(C, row + 8, col, v2, v3);
                } else {
                    __half* C = (__half*)Cv2;
                    store_Vfrag16(C, row,     col - 1024, v0);
                    store_Vfrag16(C, row,     col - 1023, v1);
                    store_Vfrag16(C, row + 8, col - 1024, v2);
                    store_Vfrag16(C, row + 8, col - 1023, v3);
                }
            }
        }
    }
}

// ---------------------------------------------------------------------------
// Flash attention fp16 (causal). 128 q rows per CTA, 8 warps x 16 rows,
// 2 CTAs/SM, 128-kpos stages, 3-stage cp.async. Warp-uniform causal skip:
// fully-masked nf (S side) and ks (PV side) are skipped exactly (contribute 0).
// ---------------------------------------------------------------------------
__global__ void __launch_bounds__(256, 2) attn_tc(
    const unsigned* __restrict__ qF, const unsigned* __restrict__ xK,
    const unsigned* __restrict__ vV, unsigned* __restrict__ attA)
{
    extern __shared__ unsigned sh[];              // 3 * 8192 uints = 96 KB
    const int tid  = threadIdx.x;
    const int lane = tid & 31;
    const int wid  = tid >> 5;
    const int g    = lane >> 2;
    const int tig  = lane & 3;

    const int qb = (gridDim.x - 1) - blockIdx.x;  // heavy q-blocks first
    const int bh = blockIdx.y;
    const int b  = bh >> 4;
    const int h  = bh & 15;
    const int q0 = qb * 128;

    const unsigned* ktiles = xK + ((size_t)bh * 32) * 2048;
    const unsigned* vtiles = vV + ((size_t)bh * 32) * 2048;
    const unsigned* qtile  = qF + ((size_t)(bh * 16 + qb)) * 4096;
    const uint32_t sbase = (uint32_t)__cvta_generic_to_shared(sh);

    const int NT = qb + 1;                        // 128-kpos tiles

    auto issue = [&](int kt) {
        int st = kt % 3;
        uint32_t sk = sbase + st * 8192 * 4;
        const unsigned* gk = ktiles + (size_t)kt * 4096;
        const unsigned* gv = vtiles + (size_t)kt * 4096;
        #pragma unroll
        for (int i = 0; i < 4; i++)
            cpasync16(sk + (tid + i * 256) * 16, gk + (tid + i * 256) * 4);
        uint32_t sv = sk + 4096 * 4;
        #pragma unroll
        for (int i = 0; i < 4; i++)
            cpasync16(sv + (tid + i * 256) * 16, gv + (tid + i * 256) * 4);
        cp_commit();
    };

    issue(0);
    if (1 < NT) issue(1);

    unsigned qa[4][4];
    #pragma unroll
    for (int ks = 0; ks < 4; ks++) {
        uint4 t = *(const uint4*)(qtile + ((ks * 8 + wid) * 32 + lane) * 4);
        qa[ks][0] = t.x; qa[ks][1] = t.y; qa[ks][2] = t.z; qa[ks][3] = t.w;
    }

    float o[8][4];
    #pragma unroll
    for (int nf = 0; nf < 8; nf++)
        #pragma unroll
        for (int r = 0; r < 4; r++) o[nf][r] = 0.f;

    float lacc[4] = {0.f, 0.f, 0.f, 0.f};
    const unsigned onesb[2] = {0x3C003C00u, 0x3C003C00u};
    const int row0   = q0 + wid * 16 + g;
    const int rowmax = q0 + wid * 16 + 15;        // warp-uniform max q row

    for (int kt = 0; kt < NT; kt++) {
        if (kt == NT - 1) asm volatile("cp.async.wait_group 0;");
        else              asm volatile("cp.async.wait_group 1;");
        __syncthreads();

        const unsigned* stage = sh + (kt % 3) * 8192;

        #pragma unroll
        for (int hh = 0; hh < 2; hh++) {
            const unsigned* Ks = stage + hh * 2048;
            const unsigned* Vs = stage + 4096 + hh * 2048;
            const int k0 = kt * 128 + hh * 64;

            // warp-uniform causal bounds (exact: skipped frags contribute 0)
            const int rel = rowmax - k0;
            const int nfmax = (rel < 0) ? 0 : ((rel >= 56) ? 8 : ((rel >> 3) + 1));
            const int ksmax = (rel < 0) ? 0 : ((rel >= 48) ? 4 : ((rel >> 4) + 1));

            float s[8][4];
            #pragma unroll
            for (int nf = 0; nf < 8; nf++)
                #pragma unroll
                for (int r = 0; r < 4; r++) s[nf][r] = -1e30f;
            #pragma unroll
            for (int nf = 0; nf < 8; nf++) {
                if (nf < nfmax) {
                    s[nf][0] = 0.f; s[nf][1] = 0.f; s[nf][2] = 0.f; s[nf][3] = 0.f;
                    #pragma unroll
                    for (int ks = 0; ks < 4; ks++) {
                        uint2 bt = *(const uint2*)(Ks + ((ks * 8 + nf) * 32 + lane) * 2);
                        unsigned bf[2] = {bt.x, bt.y};
                        mma_f16(s[nf], qa[ks], bf);
                    }
                }
            }

            // per-lane causal mask (diagonal tiles only)
            if (k0 + 63 > row0) {
                #pragma unroll
                for (int nf = 0; nf < 8; nf++) {
                    int col = k0 + nf * 8 + 2 * tig;
                    if (col     > row0)     s[nf][0] = -1e30f;
                    if (col + 1 > row0)     s[nf][1] = -1e30f;
                    if (col     > row0 + 8) s[nf][2] = -1e30f;
                    if (col + 1 > row0 + 8) s[nf][3] = -1e30f;
                }
            }

            unsigned pa[4][4];
            #pragma unroll
            for (int ks = 0; ks < 4; ks++) {
                pa[ks][0] = ex2h2(packh2(s[2 * ks    ][0], s[2 * ks    ][1]));
                pa[ks][1] = ex2h2(packh2(s[2 * ks    ][2], s[2 * ks    ][3]));
                pa[ks][2] = ex2h2(packh2(s[2 * ks + 1][0], s[2 * ks + 1][1]));
                pa[ks][3] = ex2h2(packh2(s[2 * ks + 1][2], s[2 * ks + 1][3]));
            }

            #pragma unroll
            for (int ks = 0; ks < 4; ks++) {
                if (ks < ksmax) {
                    #pragma unroll
                    for (int nf = 0; nf < 8; nf++) {
                        uint2 bt = *(const uint2*)(Vs + ((ks * 8 + nf) * 32 + lane) * 2);
                        unsigned bf[2] = {bt.x, bt.y};
                        mma_f16(o[nf], pa[ks], bf);
                    }
                    mma_f16(lacc, pa[ks], onesb);
                }
            }
        }

        if (kt + 2 < NT) issue(kt + 2);
    }

    float il0 = 1.f / lacc[0], il1 = 1.f / lacc[2];
    const int rowg0 = (b << 11) + q0 + wid * 16 + g;
    const int rowg1 = rowg0 + 8;
    #pragma unroll
    for (int nf = 0; nf < 8; nf++) {
        int e = h * 64 + nf * 8 + 2 * tig;
        store_Afrag16(attA, rowg0, e, o[nf][0] * il0, o[nf][1] * il0);
        store_Afrag16(attA, rowg1, e, o[nf][2] * il1, o[nf][3] * il1);
    }
}

// ---------------------------------------------------------------------------
// Launch
// ---------------------------------------------------------------------------
extern "C" void kernel_launch(void* const* d_in, const int* in_sizes, int n_in,
                              void* d_out, int out_size)
{
    const float* x        = (const float*)d_in[0];
    const float* c_attn_w = (const float*)d_in[1];
    const float* c_attn_b = (const float*)d_in[2];
    const float* c_proj_w = (const float*)d_in[3];
    const float* c_proj_b = (const float*)d_in[4];
    float* out = (float*)d_out;

    unsigned *xA, *attA, *qF, *xK, *vV, *wqA, *wqvB, *wkB, *wpB;
    float *wpart, *bqv;
    cudaGetSymbolAddress((void**)&xA,    g_xA);
    cudaGetSymbolAddress((void**)&attA,  g_attA);
    cudaGetSymbolAddress((void**)&qF,    g_qF);
    cudaGetSymbolAddress((void**)&xK,    g_xK);
    cudaGetSymbolAddress((void**)&vV,    g_vV);
    cudaGetSymbolAddress((void**)&wqA,   g_wqA);
    cudaGetSymbolAddress((void**)&wqvB,  g_wqvB);
    cudaGetSymbolAddress((void**)&wkB,   g_wkB);
    cudaGetSymbolAddress((void**)&wpB,   g_wpB);
    cudaGetSymbolAddress((void**)&wpart, g_wpart);
    cudaGetSymbolAddress((void**)&bqv,   g_bqv);

    const int gemm_smem = 3 * 8192 * 4;   // 96 KB (x2 CTAs = 192 KB/SM)
    const int attn_smem = 3 * 8192 * 4;   // 96 KB (x2 CTAs = 192 KB/SM)
    static cudaStream_t s2 = nullptr;
    static cudaEvent_t  evA = nullptr, evB = nullptr;
    static int attr_set = 0;
    if (!attr_set) {
        cudaFuncSetAttribute(gemm_frag<0>,
                             cudaFuncAttributeMaxDynamicSharedMemorySize, gemm_smem);
        cudaFuncSetAttribute(gemm_frag<5>,
                             cudaFuncAttributeMaxDynamicSharedMemorySize, gemm_smem);
        cudaFuncSetAttribute(gemm_frag<7>,
                             cudaFuncAttributeMaxDynamicSharedMemorySize, gemm_smem);
        cudaFuncSetAttribute(attn_tc,
                             cudaFuncAttributeMaxDynamicSharedMemorySize, attn_smem);
        cudaStreamCreateWithFlags(&s2, cudaStreamNonBlocking);
        cudaEventCreateWithFlags(&evA, cudaEventDisableTiming);
        cudaEventCreateWithFlags(&evB, cudaEventDisableTiming);
        attr_set = 1;
    }

    // minimal weight conversion for the W' chain
    convW1<<<2048, 256>>>(c_attn_w, wqA, wkB);

    // fork: W' chain on s2, overlapped with convX2 on main stream
    cudaEventRecord(evA, 0);
    cudaStreamWaitEvent(s2, evA, 0);
    dim3 gwp(8, 8, 8);
    gemm_frag<7><<<gwp, 256, gemm_smem, s2>>>(wqA, wkB, nullptr, wpart, nullptr, 2);
    convWp<<<2048, 256, 0, s2>>>(wpart, c_attn_w, c_attn_b, wqvB, bqv);
    cudaEventRecord(evB, s2);

    // x conversion + remaining weight conversions
    convX2<<<6148, 256>>>(x, c_attn_w, c_proj_w, c_attn_b,
                          xA, xK, wqvB, wpB, bqv);

    // join before the fused dual GEMM
    cudaStreamWaitEvent(0, evB, 0);

    // fused q|v GEMM: x @ [W' | Wv] + [b' | vb] -> qF (Q-frags) + vV (V-frags)
    dim3 gqv(2 * Eq / 128, Mq / 128);   // (16, 32)
    gemm_frag<5><<<gqv, 256, gemm_smem>>>(xA, wqvB, bqv, qF, vV, 16);

    // flash attention (causal)  -> GEMM-A frags
    dim3 agrid(Sq / 128, Bq * Hq);      // (16, 32)
    attn_tc<<<agrid, 256, attn_smem>>>(qF, xK, vV, attA);

    // out = att @ Wproj + bproj -> fp32
    dim3 ggrid(Eq / 128, Mq / 128);     // (8, 32)
    gemm_frag<0><<<ggrid, 256, gemm_smem>>>(attA, wpB, c_proj_b, out, nullptr, 16);
}

// round 16
// speedup vs baseline: 1.0104x; 1.0104x over previous
#include <cuda_runtime.h>
#include <cuda_fp16.h>
#include <cstddef>
#include <cstdint>

// Problem constants
#define Bq   2
#define Sq   2048
#define Eq   1024
#define Hq   16
#define Dq   64
#define Mq   (Bq*Sq)          // 4096

// ---------------------------------------------------------------------------
// Scratch (device globals; no allocations allowed)
// ---------------------------------------------------------------------------
__device__ unsigned g_xA  [(size_t)Mq*Eq/2];     // x   as GEMM-A frags
__device__ unsigned g_attA[(size_t)Mq*Eq/2];     // att as GEMM-A frags
__device__ unsigned g_qF  [(size_t)Mq*Eq/2];     // q   as attn-Q frags (scaled)
__device__ unsigned g_xK  [(size_t)Mq*Eq/2];     // x   as attn-K frags
__device__ unsigned g_vV  [(size_t)Mq*Eq/2];     // v   as attn-V frags
__device__ unsigned g_wqA [(size_t)Eq*Eq/2];     // Wq   as GEMM-A frags
__device__ unsigned g_wqvB[(size_t)Eq*2*Eq/2];   // W' | Wv as B-frags (2048 n)
__device__ unsigned g_wkB [(size_t)Eq*Eq/2];     // Wk   as B-frags
__device__ unsigned g_wpB [(size_t)Eq*Eq/2];     // Wp   as B-frags
__device__ float    g_wpart[(size_t)4*Eq*Eq];    // W' split-K fp32 partials
__device__ float    g_bqv [2 * Eq];              // b' | vb fused bias

// ---------------------------------------------------------------------------
// helpers
// ---------------------------------------------------------------------------
__device__ __forceinline__ unsigned packh2(float lo, float hi) {
    unsigned r;
    asm("cvt.rn.f16x2.f32 %0, %1, %2;" : "=r"(r) : "f"(hi), "f"(lo));
    return r;
}
__device__ __forceinline__ unsigned ex2h2(unsigned a) {
    unsigned r;
    asm("ex2.approx.f16x2 %0, %1;" : "=r"(r) : "r"(a));
    return r;
}
__device__ __forceinline__ void mma_f16(float* c, const unsigned* a, const unsigned* b) {
    asm volatile(
        "mma.sync.aligned.m16n8k16.row.col.f32.f16.f16.f32 "
        "{%0,%1,%2,%3}, {%4,%5,%6,%7}, {%8,%9}, {%0,%1,%2,%3};"
        : "+f"(c[0]), "+f"(c[1]), "+f"(c[2]), "+f"(c[3])
        : "r"(a[0]), "r"(a[1]), "r"(a[2]), "r"(a[3]),
          "r"(b[0]), "r"(b[1]));
}
__device__ __forceinline__ void cpasync16(uint32_t s, const void* g) {
    asm volatile("cp.async.cg.shared.global [%0], [%1], 16;" :: "r"(s), "l"(g));
}
__device__ __forceinline__ void cp_commit() {
    asm volatile("cp.async.commit_group;");
}

// ---------------------------------------------------------------------------
// fp16 fragment-store helpers (validated)
// ---------------------------------------------------------------------------
__device__ __forceinline__ void store_Afrag16(unsigned* C, int row, int k,
                                              float v0, float v1) {
    size_t tile = (size_t)(row >> 7) * 32 + (k >> 5);
    int m = row & 127, klo = k & 15, kstep = (k >> 4) & 1;
    int inner = ((kstep * 8 + (m >> 4)) * 32 + (m & 7) * 4 + ((klo >> 1) & 3)) * 4
              + ((m >> 3) & 1) + 2 * (klo >> 3);
    C[tile * 2048 + inner] = packh2(v0, v1);
}
// attn Q-frag: pre-scaled by (1/8)*log2(e) so attention uses ex2 directly
__device__ __forceinline__ void store_Qfrag16(unsigned* C, int row, int col,
                                              float v0, float v1) {
    const float QS = 0.125f * 1.4426950408889634f;
    int b = row >> 11, s2 = row & 2047, qt = s2 >> 7, sr = s2 & 127;
    int h = col >> 6, d = col & 63;
    size_t tile = (size_t)((b << 4) + h) * 16 + qt;
    int dlo = d & 15, kstep = d >> 4;
    int inner = ((kstep * 8 + (sr >> 4)) * 32 + (sr & 7) * 4 + ((dlo >> 1) & 3)) * 4
              + ((sr >> 3) & 1) + 2 * (dlo >> 3);
    C[tile * 4096 + inner] = packh2(v0 * QS, v1 * QS);
}
__device__ __forceinline__ void store_Vfrag16(__half* C16, int row, int col, float val) {
    int b = row >> 11, s2 = row & 2047, kt = s2 >> 6, kp = s2 & 63;
    int h = col >> 6, d = col & 63;
    size_t tile = (size_t)((b << 4) + h) * 32 + kt;
    int klo = kp & 15, kstep = kp >> 4;
    int inner = ((kstep * 8 + (d >> 3)) * 32 + (d & 7) * 4 + ((klo >> 1) & 3)) * 2
              + (klo >> 3);
    C16[tile * 4096 + inner * 2 + (klo & 1)] = __float2half_rn(val);
}

// ---------------------------------------------------------------------------
// Conversion bodies (validated)
// ---------------------------------------------------------------------------
__device__ __forceinline__ void convB_body(const float* B, unsigned* dst, int ldb, int idx)
{
    int k  = idx >> 8;
    int n4 = (idx & 255) << 2;
    float4 t = *(const float4*)(B + (size_t)k * ldb + n4);
    float tv[4] = {t.x, t.y, t.z, t.w};
    int klo = k & 15, kstep = (k >> 4) & 1;
    __half* d16 = (__half*)dst;
    #pragma unroll
    for (int j = 0; j < 4; j++) {
        int n = n4 + j;
        size_t tile = ((size_t)(n >> 8) * 32 + (k >> 5));
        int inner = ((kstep * 32 + ((n >> 3) & 31)) * 32 + (n & 7) * 4 + ((klo >> 1) & 3)) * 2
                  + (klo >> 3);
        d16[tile * 8192 + inner * 2 + (klo & 1)] = __float2half_rn(tv[j]);
    }
}
__device__ __forceinline__ void convBT_body(const float* B, unsigned* dst, int ldb, int idx)
{
    int n  = idx >> 8;
    int k4 = (idx & 255) << 2;
    float4 t = *(const float4*)(B + (size_t)n * ldb + k4);
    int nfrag = (n >> 3) & 31, g = n & 7;
    #pragma unroll
    for (int p = 0; p < 2; p++) {
        int k = k4 + 2 * p;
        int klo = k & 15, kstep = (k >> 4) & 1;
        size_t tile = ((size_t)(n >> 8) * 32 + (k >> 5));
        int inner = ((kstep * 32 + nfrag) * 32 + g * 4 + ((klo >> 1) & 3)) * 2
                  + (klo >> 3);
        dst[tile * 4096 + inner] = (p == 0) ? packh2(t.x, t.y) : packh2(t.z, t.w);
    }
}

// ---------------------------------------------------------------------------
// Weight conversions (blocks 0..4095) + vb copy (blocks 4096..4099)
// ---------------------------------------------------------------------------
__global__ void convW(const float* __restrict__ aw, const float* __restrict__ pw,
                      const float* __restrict__ ab,
                      unsigned* __restrict__ wqA, unsigned* __restrict__ wqv,
                      unsigned* __restrict__ wk, unsigned* __restrict__ wp,
                      float* __restrict__ bqv)
{
    int bx = blockIdx.x;
    if (bx >= 4096) {
        int i = (bx - 4096) * 256 + threadIdx.x;
        bqv[1024 + i] = ab[2048 + i];
        return;
    }
    int which = bx >> 10;
    int idx = (bx & 1023) * 256 + threadIdx.x;
    if (which == 0) {
        int m = idx >> 8, n4 = (idx & 255) << 2;
        float4 t = *(const float4*)(aw + (size_t)m * 3072 + n4);
        store_Afrag16(wqA, m, n4,     t.x, t.y);
        store_Afrag16(wqA, m, n4 + 2, t.z, t.w);
    }
    else if (which == 1) convB_body (aw + 2 * Eq, wqv + (size_t)4 * 32 * 4096, 3 * Eq, idx);
    else if (which == 2) convBT_body(aw + Eq,     wk,                          3 * Eq, idx);
    else                 convB_body (pw,          wp,                          Eq,     idx);
}

// ---------------------------------------------------------------------------
// x conversion: GEMM-A frags + attention-K frags
// ---------------------------------------------------------------------------
__global__ void convX(const float* __restrict__ x,
                      unsigned* __restrict__ xA, unsigned* __restrict__ xK)
{
    int idx = blockIdx.x * 256 + threadIdx.x;
    int m   = idx >> 8;
    int e4  = (idx & 255) << 2;
    float4 t = *(const float4*)(x + (size_t)m * Eq + e4);

    store_Afrag16(xA, m, e4,     t.x, t.y);
    store_Afrag16(xA, m, e4 + 2, t.z, t.w);

    int s = m & (Sq - 1), b = m >> 11;
    int h = e4 >> 6, d4 = e4 & 63;
    int kt = s >> 6, kp = s & 63;
    unsigned* tile = xK + ((size_t)((b << 4) + h) * 32 + kt) * 2048;
    float tv[4] = {t.x, t.y, t.z, t.w};
    #pragma unroll
    for (int p = 0; p < 2; p++) {
        int d = d4 + 2 * p;
        int dlo = d & 15, kstep = d >> 4;
        int inner = ((kstep * 8 + (kp >> 3)) * 32 + (kp & 7) * 4 + ((dlo >> 1) & 3)) * 2
                  + (dlo >> 3);
        tile[inner] = packh2(tv[2 * p], tv[2 * p + 1]);
    }
}

// ---------------------------------------------------------------------------
// W' finalize: blocks 0..1023 sum split-K partials -> B-frags (wqv first half)
//              blocks 1024..2047 compute b'[j] = bq . Wk[j,:] + kb[j]
// ---------------------------------------------------------------------------
__global__ void convWp(const float* __restrict__ wpart,
                       const float* __restrict__ aw, const float* __restrict__ ab,
                       unsigned* __restrict__ wqv, float* __restrict__ bqv)
{
    int bx = blockIdx.x;
    if (bx < 1024) {
        int idx = bx * 256 + threadIdx.x;
        int k = idx >> 8, n4 = (idx & 255) << 2;
        size_t off = (size_t)k * 1024 + n4;
        float4 p0 = *(const float4*)(wpart + off);
        float4 p1 = *(const float4*)(wpart + off + 1048576);
        float4 p2 = *(const float4*)(wpart + off + 2097152);
        float4 p3 = *(const float4*)(wpart + off + 3145728);
        float tv[4] = {p0.x + p1.x + p2.x + p3.x, p0.y + p1.y + p2.y + p3.y,
                       p0.z + p1.z + p2.z + p3.z, p0.w + p1.w + p2.w + p3.w};
        int klo = k & 15, kstep = (k >> 4) & 1;
        __half* d16 = (__half*)wqv;
        #pragma unroll
        for (int j = 0; j < 4; j++) {
            int n = n4 + j;
            size_t tile = ((size_t)(n >> 8) * 32 + (k >> 5));
            int inner = ((kstep * 32 + ((n >> 3) & 31)) * 32 + (n & 7) * 4
                         + ((klo >> 1) & 3)) * 2 + (klo >> 3);
            d16[tile * 8192 + inner * 2 + (klo & 1)] = __float2half_rn(tv[j]);
        }
        return;
    }
    // b'[j]
    int j = bx - 1024;
    __shared__ float red[256];
    int tid = threadIdx.x;
    float sum = 0.f;
    #pragma unroll
    for (int i = 0; i < 4; i++) {
        int n = tid + i * 256;
        sum += ab[n] * aw[(size_t)j * 3072 + 1024 + n];
    }
    red[tid] = sum;
    __syncthreads();
    for (int s = 128; s > 0; s >>= 1) {
        if (tid < s) red[tid] += red[tid + s];
        __syncthreads();
    }
    if (tid == 0) bqv[j] = red[0] + ab[1024 + j];
}

// ---------------------------------------------------------------------------
// GEMM fp16: CTA 128m x 128n, K-stage 64, 3-stage cp.async, 256 thr, 2 CTA/SM.
// MODE: 0 = fp32 row-major (+bias)
//       5 = dual: col<1024 -> Q-frag to Cv, else V-frag to Cv2 (+bias)
//       7 = fp32 partial to Cv + z*1M, no bias, kbase = z*nst
// ---------------------------------------------------------------------------
template<int MODE>
__global__ void __launch_bounds__(256, 2) gemm_frag(
    const unsigned* __restrict__ Afrag, const unsigned* __restrict__ Bfrag,
    const float* __restrict__ bias, void* __restrict__ Cv, void* __restrict__ Cv2,
    int nst)
{
    extern __shared__ unsigned sh[];              // 3 * 8192 uints = 96 KB
    const int tid  = threadIdx.x;
    const int lane = tid & 31;
    const int wid  = tid >> 5;
    const int wm   = wid & 1;
    const int wn   = wid >> 1;
    const int g    = lane >> 2;
    const int tig  = lane & 3;
    const int m0   = blockIdx.y * 128;
    const int n0   = blockIdx.x * 128;
    const int nhalf = blockIdx.x & 1;
    const int kbase = (MODE == 7) ? blockIdx.z * nst : 0;

    const unsigned* gA = Afrag + (size_t)blockIdx.y * 32 * 2048;
    const unsigned* gB = Bfrag + (size_t)(blockIdx.x >> 1) * 32 * 4096;
    const uint32_t sbase = (uint32_t)__cvta_generic_to_shared(sh);

    auto issue = [&](int st) {
        int sl = st % 3;
        uint32_t sa = sbase + sl * 8192 * 4;
        const unsigned* ga = gA + (size_t)(2 * (kbase + st)) * 2048;
        #pragma unroll
        for (int i = 0; i < 4; i++)
            cpasync16(sa + (tid + i * 256) * 16, ga + (tid + i * 256) * 4);
        uint32_t sb = sa + 4096 * 4;
        #pragma unroll
        for (int c = 0; c < 4; c++) {
            int h = c >> 1, kst = c & 1;
            const unsigned* gb = gB + (size_t)(2 * (kbase + st) + h) * 4096
                               + kst * 2048 + nhalf * 1024;
            cpasync16(sb + (c * 1024 + tid * 4) * 4, gb + tid * 4);
        }
        cp_commit();
    };

    float acc[4][4][4];
    #pragma unroll
    for (int mi = 0; mi < 4; mi++)
        #pragma unroll
        for (int ni = 0; ni < 4; ni++)
            #pragma unroll
            for (int r = 0; r < 4; r++) acc[mi][ni][r] = 0.f;

    issue(0);
    issue(1);

    for (int st = 0; st < nst; st++) {
        if (st == nst - 1) asm volatile("cp.async.wait_group 0;");
        else               asm volatile("cp.async.wait_group 1;");
        __syncthreads();

        const unsigned* stage = sh + (st % 3) * 8192;
        #pragma unroll
        for (int half = 0; half < 2; half++) {
            const unsigned* as = stage + half * 2048;
            const unsigned* bs = stage + 4096 + half * 2048;
            #pragma unroll
            for (int ks = 0; ks < 2; ks++) {
                unsigned af[4][4], bf[4][2];
                #pragma unroll
                for (int mi = 0; mi < 4; mi++) {
                    uint4 t = *(const uint4*)(as + ((ks * 8 + wm * 4 + mi) * 32 + lane) * 4);
                    af[mi][0] = t.x; af[mi][1] = t.y; af[mi][2] = t.z; af[mi][3] = t.w;
                }
                #pragma unroll
                for (int ni = 0; ni < 4; ni++) {
                    uint2 t = *(const uint2*)(bs + ks * 1024
                                              + ((wn * 4 + ni) * 32 + lane) * 2);
                    bf[ni][0] = t.x; bf[ni][1] = t.y;
                }
                #pragma unroll
                for (int mi = 0; mi < 4; mi++)
                    #pragma unroll
                    for (int ni = 0; ni < 4; ni++)
                        mma_f16(acc[mi][ni], af[mi], bf[ni]);
            }
        }

        if (st + 2 < nst) issue(st + 2);
    }

    // epilogue
    #pragma unroll
    for (int ni = 0; ni < 4; ni++) {
        int col = n0 + wn * 32 + ni * 8 + 2 * tig;
        float b0 = 0.f, b1 = 0.f;
        if (MODE != 7) { b0 = bias[col]; b1 = bias[col + 1]; }
        #pragma unroll
        for (int mi = 0; mi < 4; mi++) {
            int row = m0 + wm * 64 + mi * 16 + g;
            float v0 = acc[mi][ni][0] + b0, v1 = acc[mi][ni][1] + b1;
            float v2 = acc[mi][ni][2] + b0, v3 = acc[mi][ni][3] + b1;
            if (MODE == 0) {
                float* C = (float*)Cv;
                *(float2*)(C + (size_t)row * Eq + col)       = make_float2(v0, v1);
                *(float2*)(C + (size_t)(row + 8) * Eq + col) = make_float2(v2, v3);
            } else if (MODE == 7) {
                float* C = (float*)Cv + (size_t)blockIdx.z * 1048576;
                *(float2*)(C + (size_t)row * Eq + col)       = make_float2(v0, v1);
                *(float2*)(C + (size_t)(row + 8) * Eq + col) = make_float2(v2, v3);
            } else {    // MODE 5: dual Q | V
                if (col < 1024) {
                    unsigned* C = (unsigned*)Cv;
                    store_Qfrag16(C, row,     col, v0, v1);
                    store_Qfrag16(C, row + 8, col, v2, v3);
                } else {
                    __half* C = (__half*)Cv2;
                    store_Vfrag16(C, row,     col - 1024, v0);
                    store_Vfrag16(C, row,     col - 1023, v1);
                    store_Vfrag16(C, row + 8, col - 1024, v2);
                    store_Vfrag16(C, row + 8, col - 1023, v3);
                }
            }
        }
    }
}

// ---------------------------------------------------------------------------
// Flash attention fp16 (causal). 128 q rows per CTA, 8 warps x 16 rows,
// 2 CTAs/SM, 128-kpos stages, 3-stage cp.async. Warp-uniform causal skip:
// fully-masked nf (S side) and ks (PV side) are skipped exactly (contribute 0).
// ---------------------------------------------------------------------------
__global__ void __launch_bounds__(256, 2) attn_tc(
    const unsigned* __restrict__ qF, const unsigned* __restrict__ xK,
    const unsigned* __restrict__ vV, unsigned* __restrict__ attA)
{
    extern __shared__ unsigned sh[];              // 3 * 8192 uints = 96 KB
    const int tid  = threadIdx.x;
    const int lane = tid & 31;
    const int wid  = tid >> 5;
    const int g    = lane >> 2;
    const int tig  = lane & 3;

    const int qb = (gridDim.x - 1) - blockIdx.x;  // heavy q-blocks first
    const int bh = blockIdx.y;
    const int b  = bh >> 4;
    const int h  = bh & 15;
    const int q0 = qb * 128;

    const unsigned* ktiles = xK + ((size_t)bh * 32) * 2048;
    const unsigned* vtiles = vV + ((size_t)bh * 32) * 2048;
    const unsigned* qtile  = qF + ((size_t)(bh * 16 + qb)) * 4096;
    const uint32_t sbase = (uint32_t)__cvta_generic_to_shared(sh);

    const int NT = qb + 1;                        // 128-kpos tiles

    auto issue = [&](int kt) {
        int st = kt % 3;
        uint32_t sk = sbase + st * 8192 * 4;
        const unsigned* gk = ktiles + (size_t)kt * 4096;
        const unsigned* gv = vtiles + (size_t)kt * 4096;
        #pragma unroll
        for (int i = 0; i < 4; i++)
            cpasync16(sk + (tid + i * 256) * 16, gk + (tid + i * 256) * 4);
        uint32_t sv = sk + 4096 * 4;
        #pragma unroll
        for (int i = 0; i < 4; i++)
            cpasync16(sv + (tid + i * 256) * 16, gv + (tid + i * 256) * 4);
        cp_commit();
    };

    issue(0);
    if (1 < NT) issue(1);

    unsigned qa[4][4];
    #pragma unroll
    for (int ks = 0; ks < 4; ks++) {
        uint4 t = *(const uint4*)(qtile + ((ks * 8 + wid) * 32 + lane) * 4);
        qa[ks][0] = t.x; qa[ks][1] = t.y; qa[ks][2] = t.z; qa[ks][3] = t.w;
    }

    float o[8][4];
    #pragma unroll
    for (int nf = 0; nf < 8; nf++)
        #pragma unroll
        for (int r = 0; r < 4; r++) o[nf][r] = 0.f;

    float lacc[4] = {0.f, 0.f, 0.f, 0.f};
    const unsigned onesb[2] = {0x3C003C00u, 0x3C003C00u};
    const int row0   = q0 + wid * 16 + g;
    const int rowmax = q0 + wid * 16 + 15;        // warp-uniform max q row

    for (int kt = 0; kt < NT; kt++) {
        if (kt == NT - 1) asm volatile("cp.async.wait_group 0;");
        else              asm volatile("cp.async.wait_group 1;");
        __syncthreads();

        const unsigned* stage = sh + (kt % 3) * 8192;

        #pragma unroll
        for (int hh = 0; hh < 2; hh++) {
            const unsigned* Ks = stage + hh * 2048;
            const unsigned* Vs = stage + 4096 + hh * 2048;
            const int k0 = kt * 128 + hh * 64;

            // warp-uniform causal bounds (exact: skipped frags contribute 0)
            const int rel = rowmax - k0;
            const int nfmax = (rel < 0) ? 0 : ((rel >= 56) ? 8 : ((rel >> 3) + 1));
            const int ksmax = (rel < 0) ? 0 : ((rel >= 48) ? 4 : ((rel >> 4) + 1));

            float s[8][4];
            #pragma unroll
            for (int nf = 0; nf < 8; nf++)
                #pragma unroll
                for (int r = 0; r < 4; r++) s[nf][r] = -1e30f;
            #pragma unroll
            for (int nf = 0; nf < 8; nf++) {
                if (nf < nfmax) {
                    s[nf][0] = 0.f; s[nf][1] = 0.f; s[nf][2] = 0.f; s[nf][3] = 0.f;
                    #pragma unroll
                    for (int ks = 0; ks < 4; ks++) {
                        uint2 bt = *(const uint2*)(Ks + ((ks * 8 + nf) * 32 + lane) * 2);
                        unsigned bf[2] = {bt.x, bt.y};
                        mma_f16(s[nf], qa[ks], bf);
                    }
                }
            }

            // per-lane causal mask (diagonal tiles only)
            if (k0 + 63 > row0) {
                #pragma unroll
                for (int nf = 0; nf < 8; nf++) {
                    int col = k0 + nf * 8 + 2 * tig;
                    if (col     > row0)     s[nf][0] = -1e30f;
                    if (col + 1 > row0)     s[nf][1] = -1e30f;
                    if (col     > row0 + 8) s[nf][2] = -1e30f;
                    if (col + 1 > row0 + 8) s[nf][3] = -1e30f;
                }
            }

            unsigned pa[4][4];
            #pragma unroll
            for (int ks = 0; ks < 4; ks++) {
                pa[ks][0] = ex2h2(packh2(s[2 * ks    ][0], s[2 * ks    ][1]));
                pa[ks][1] = ex2h2(packh2(s[2 * ks    ][2], s[2 * ks    ][3]));
                pa[ks][2] = ex2h2(packh2(s[2 * ks + 1][0], s[2 * ks + 1][1]));
                pa[ks][3] = ex2h2(packh2(s[2 * ks + 1][2], s[2 * ks + 1][3]));
            }

            #pragma unroll
            for (int ks = 0; ks < 4; ks++) {
                if (ks < ksmax) {
                    #pragma unroll
                    for (int nf = 0; nf < 8; nf++) {
                        uint2 bt = *(const uint2*)(Vs + ((ks * 8 + nf) * 32 + lane) * 2);
                        unsigned bf[2] = {bt.x, bt.y};
                        mma_f16(o[nf], pa[ks], bf);
                    }
                    mma_f16(lacc, pa[ks], onesb);
                }
            }
        }

        if (kt + 2 < NT) issue(kt + 2);
    }

    float il0 = 1.f / lacc[0], il1 = 1.f / lacc[2];
    const int rowg0 = (b << 11) + q0 + wid * 16 + g;
    const int rowg1 = rowg0 + 8;
    #pragma unroll
    for (int nf = 0; nf < 8; nf++) {
        int e = h * 64 + nf * 8 + 2 * tig;
        store_Afrag16(attA, rowg0, e, o[nf][0] * il0, o[nf][1] * il0);
        store_Afrag16(attA, rowg1, e, o[nf][2] * il1, o[nf][3] * il1);
    }
}

// ---------------------------------------------------------------------------
// Launch (round-14 proven schedule)
// ---------------------------------------------------------------------------
extern "C" void kernel_launch(void* const* d_in, const int* in_sizes, int n_in,
                              void* d_out, int out_size)
{
    const float* x        = (const float*)d_in[0];
    const float* c_attn_w = (const float*)d_in[1];
    const float* c_attn_b = (const float*)d_in[2];
    const float* c_proj_w = (const float*)d_in[3];
    const float* c_proj_b = (const float*)d_in[4];
    float* out = (float*)d_out;

    unsigned *xA, *attA, *qF, *xK, *vV, *wqA, *wqvB, *wkB, *wpB;
    float *wpart, *bqv;
    cudaGetSymbolAddress((void**)&xA,    g_xA);
    cudaGetSymbolAddress((void**)&attA,  g_attA);
    cudaGetSymbolAddress((void**)&qF,    g_qF);
    cudaGetSymbolAddress((void**)&xK,    g_xK);
    cudaGetSymbolAddress((void**)&vV,    g_vV);
    cudaGetSymbolAddress((void**)&wqA,   g_wqA);
    cudaGetSymbolAddress((void**)&wqvB,  g_wqvB);
    cudaGetSymbolAddress((void**)&wkB,   g_wkB);
    cudaGetSymbolAddress((void**)&wpB,   g_wpB);
    cudaGetSymbolAddress((void**)&wpart, g_wpart);
    cudaGetSymbolAddress((void**)&bqv,   g_bqv);

    const int gemm_smem = 3 * 8192 * 4;   // 96 KB (x2 CTAs = 192 KB/SM)
    const int attn_smem = 3 * 8192 * 4;   // 96 KB (x2 CTAs = 192 KB/SM)
    static cudaStream_t s2 = nullptr;
    static cudaEvent_t  evA = nullptr, evB = nullptr;
    static int attr_set = 0;
    if (!attr_set) {
        cudaFuncSetAttribute(gemm_frag<0>,
                             cudaFuncAttributeMaxDynamicSharedMemorySize, gemm_smem);
        cudaFuncSetAttribute(gemm_frag<5>,
                             cudaFuncAttributeMaxDynamicSharedMemorySize, gemm_smem);
        cudaFuncSetAttribute(gemm_frag<7>,
                             cudaFuncAttributeMaxDynamicSharedMemorySize, gemm_smem);
        cudaFuncSetAttribute(attn_tc,
                             cudaFuncAttributeMaxDynamicSharedMemorySize, attn_smem);
        cudaStreamCreateWithFlags(&s2, cudaStreamNonBlocking);
        cudaEventCreateWithFlags(&evA, cudaEventDisableTiming);
        cudaEventCreateWithFlags(&evB, cudaEventDisableTiming);
        attr_set = 1;
    }

    // weight conversions (+ vb copy) on main stream
    convW<<<4100, 256>>>(c_attn_w, c_proj_w, c_attn_b, wqA, wqvB, wkB, wpB, bqv);

    // fork: W' chain on s2, overlapped with convX on main stream
    cudaEventRecord(evA, 0);
    cudaStreamWaitEvent(s2, evA, 0);
    dim3 gwp(8, 8, 4);
    gemm_frag<7><<<gwp, 256, gemm_smem, s2>>>(wqA, wkB, nullptr, wpart, nullptr, 4);
    convWp<<<2048, 256, 0, s2>>>(wpart, c_attn_w, c_attn_b, wqvB, bqv);
    cudaEventRecord(evB, s2);

    convX<<<4096, 256>>>(x, xA, xK);

    // join before the fused dual GEMM
    cudaStreamWaitEvent(0, evB, 0);

    // fused q|v GEMM: x @ [W' | Wv] + [b' | vb] -> qF (Q-frags) + vV (V-frags)
    dim3 gqv(2 * Eq / 128, Mq / 128);   // (16, 32)
    gemm_frag<5><<<gqv, 256, gemm_smem>>>(xA, wqvB, bqv, qF, vV, 16);

    // flash attention (causal)  -> GEMM-A frags
    dim3 agrid(Sq / 128, Bq * Hq);      // (16, 32)
    attn_tc<<<agrid, 256, attn_smem>>>(qF, xK, vV, attA);

    // out = att @ Wproj + bproj -> fp32
    dim3 ggrid(Eq / 128, Mq / 128);     // (8, 32)
    gemm_frag<0><<<ggrid, 256, gemm_smem>>>(attA, wpB, c_proj_b, out, nullptr, 16);
}